// round 9
// baseline (speedup 1.0000x reference)
#include <cuda_runtime.h>
#include <math.h>

#define BATCH   64
#define IN_F    512
#define OUT_F   512

// Scratch (no allocations allowed -> __device__ globals)
__device__ float gW[OUT_F * IN_F];        // scaled masked w, row-major
__device__ float gInT[IN_F * BATCH];      // gInT[k][b] = inputs[b][k]
__device__ float gA[8 * 64 * 64];         // gA[d][i][o] = exp(g[d,o,i]) = scaled diag block
__device__ float gPart[8 * BATCH * OUT_F];// out partials [kc][b][r]

// ---------------------------------------------------------------------------
// K1: bid < 64 : warp-per-row weight prep, REGISTER-ONLY (no smem/syncs).
//       u = exp(W) on diag / W below / 0 above; wsn = warp butterfly;
//       scale = exp(diag_w)*rsqrt(wsn); coalesced float4 STG to gW row-major.
//       gA (= scaled diag block, algebraic identity) small scattered stores.
//     bid >= 64 (8 CTAs): warp-per-batch input transpose -> gInT.
// ---------------------------------------------------------------------------
__global__ void __launch_bounds__(256) k_weights(const float* __restrict__ W,
                                                 const float* __restrict__ diag_w,
                                                 const float* __restrict__ inputs) {
    const int tid  = threadIdx.x;
    const int w    = tid >> 5;
    const int lane = tid & 31;

    if (blockIdx.x >= 64) {
        // -------- input transpose: 8 warps, warp = one batch row --------
        const int b = (blockIdx.x - 64) * 8 + w;
        #pragma unroll
        for (int m = 0; m < 4; m++) {
            const int c0 = lane * 4 + m * 128;
            const float4 v = *(const float4*)(inputs + b * IN_F + c0);
            gInT[(c0 + 0) * BATCH + b] = v.x;
            gInT[(c0 + 1) * BATCH + b] = v.y;
            gInT[(c0 + 2) * BATCH + b] = v.z;
            gInT[(c0 + 3) * BATCH + b] = v.w;
        }
        return;
    }

    const int r  = blockIdx.x * 8 + w;
    const int rb = r >> 6;
    const int lo = rb << 6;
    const int hi = lo + 64;

    float uu[4][4];
    float ss = 0.f;
    #pragma unroll
    for (int m = 0; m < 4; m++) {
        const int c0 = lane * 4 + m * 128;
        const float4 v = *(const float4*)(W + r * IN_F + c0);
        const float vv[4] = {v.x, v.y, v.z, v.w};
        #pragma unroll
        for (int j = 0; j < 4; j++) {
            const int c = c0 + j;
            float u;
            if (c >= hi)      u = 0.f;
            else if (c >= lo) u = __expf(vv[j]);
            else              u = vv[j];
            uu[m][j] = u;
            ss += u * u;
        }
    }
    #pragma unroll
    for (int off = 16; off > 0; off >>= 1)
        ss += __shfl_xor_sync(0xffffffffu, ss, off);
    const float scale = __expf(diag_w[r]) * rsqrtf(ss);

    const int o = r - lo;
    #pragma unroll
    for (int m = 0; m < 4; m++) {
        const int c0 = lane * 4 + m * 128;
        float4 o4 = make_float4(scale * uu[m][0], scale * uu[m][1],
                                scale * uu[m][2], scale * uu[m][3]);
        *(float4*)(gW + r * IN_F + c0) = o4;
        const float ov[4] = {o4.x, o4.y, o4.z, o4.w};
        #pragma unroll
        for (int j = 0; j < 4; j++) {
            const int c = c0 + j;
            if (c >= lo && c < hi)
                gA[(rb * 64 + (c - lo)) * 64 + o] = ov[j];   // [d][i][o]
        }
    }
}

// ---------------------------------------------------------------------------
// K2 fused, 256 threads:
//   bid <  64 : out partial, CTA = (rt, kc); smem-transposed fills from gW
//   bid >= 64 : jac for (b,d) pair jbid = bid-64  (proven loop, untouched)
// ---------------------------------------------------------------------------
__global__ void __launch_bounds__(256) k_main(
        const float* __restrict__ grad,
        float* __restrict__ outp) {
    __shared__ float smemBuf[8704];
    const int bid = blockIdx.x;
    const int tid = threadIdx.x;

    if (bid >= 64) {
        // ---------------- jac: C = gA[d]^T @ exp(grad_b);  log ----------------
        const int jbid = bid - 64;       // = b*8 + d
        const int d    = jbid & 7;
        float* As = smemBuf;             // [i][o]  64x64
        float* Bs = smemBuf + 4096;      // [i][k]  64x64

        const float4* a4 = (const float4*)(gA + d * 4096);
        const float4* g4 = (const float4*)(grad + jbid * 4096);
        float4* As4 = (float4*)As;
        float4* Bs4 = (float4*)Bs;
        #pragma unroll
        for (int idx = tid; idx < 1024; idx += 256) {
            As4[idx] = a4[idx];
            const float4 v = g4[idx];
            Bs4[idx] = make_float4(__expf(v.x), __expf(v.y), __expf(v.z), __expf(v.w));
        }
        __syncthreads();

        const int k_t = tid & 15;        // 16 x4 -> 64 k
        const int o_t = tid >> 4;        // 16 x4 -> 64 o
        float acc[4][4] = {};
        const float* ap = As + o_t * 4;
        const float* bp = Bs + k_t * 4;
        #pragma unroll 8
        for (int ii = 0; ii < 64; ii++) {
            const float4 a  = *(const float4*)(ap + ii * 64);
            const float4 bv = *(const float4*)(bp + ii * 64);
            acc[0][0] += a.x * bv.x; acc[0][1] += a.x * bv.y; acc[0][2] += a.x * bv.z; acc[0][3] += a.x * bv.w;
            acc[1][0] += a.y * bv.x; acc[1][1] += a.y * bv.y; acc[1][2] += a.y * bv.z; acc[1][3] += a.y * bv.w;
            acc[2][0] += a.z * bv.x; acc[2][1] += a.z * bv.y; acc[2][2] += a.z * bv.z; acc[2][3] += a.z * bv.w;
            acc[3][0] += a.w * bv.x; acc[3][1] += a.w * bv.y; acc[3][2] += a.w * bv.z; acc[3][3] += a.w * bv.w;
        }

        float* jb = outp + 32768 + jbid * 4096;   // jac block [o][k]
        #pragma unroll
        for (int jo = 0; jo < 4; jo++) {
            const int o = o_t * 4 + jo;
            float4 v = make_float4(__logf(acc[jo][0]), __logf(acc[jo][1]),
                                   __logf(acc[jo][2]), __logf(acc[jo][3]));
            *(float4*)(jb + o * 64 + k_t * 4) = v;
        }
    } else {
        // ---------------- out partial: 64r x 64b over one 64-k chunk ----------
        const int rt = bid & 7;
        const int kc = bid >> 3;
        float* sWT  = smemBuf;              // [kk][r] 64x68
        float* sInT = smemBuf + 64 * 68;    // [kk][b] 64x68

        // W fill: coalesced LDG from row-major gW, transposed STS
        #pragma unroll
        for (int m = 0; m < 4; m++) {
            const int idx = tid + 256 * m;            // 1024 float4
            const int rr = idx >> 4, kq = (idx & 15) * 4;
            const float4 v = *(const float4*)(gW + (rt * 64 + rr) * IN_F + kc * 64 + kq);
            sWT[(kq + 0) * 68 + rr] = v.x;
            sWT[(kq + 1) * 68 + rr] = v.y;
            sWT[(kq + 2) * 68 + rr] = v.z;
            sWT[(kq + 3) * 68 + rr] = v.w;
        }
        // inputs fill: already transposed in gInT, straight copy
        #pragma unroll
        for (int m = 0; m < 4; m++) {
            const int idx = tid + 256 * m;
            const int kk = idx >> 4, c4 = (idx & 15) * 4;
            *(float4*)(sInT + kk * 68 + c4) =
                *(const float4*)(gInT + (kc * 64 + kk) * BATCH + c4);
        }
        __syncthreads();

        const int b4 = (tid & 15) * 4;   // 16 -> 64 b
        const int r4 = (tid >> 4) * 4;   // 16 -> 64 r
        float acc[4][4] = {};            // [bi][ri]
        const float* ip = sInT + b4;
        const float* wp = sWT + r4;
        #pragma unroll 8
        for (int kk = 0; kk < 64; kk++) {
            const float4 iv = *(const float4*)(ip + kk * 68);
            const float4 wv = *(const float4*)(wp + kk * 68);
            acc[0][0] += iv.x * wv.x; acc[0][1] += iv.x * wv.y; acc[0][2] += iv.x * wv.z; acc[0][3] += iv.x * wv.w;
            acc[1][0] += iv.y * wv.x; acc[1][1] += iv.y * wv.y; acc[1][2] += iv.y * wv.z; acc[1][3] += iv.y * wv.w;
            acc[2][0] += iv.z * wv.x; acc[2][1] += iv.z * wv.y; acc[2][2] += iv.z * wv.z; acc[2][3] += iv.z * wv.w;
            acc[3][0] += iv.w * wv.x; acc[3][1] += iv.w * wv.y; acc[3][2] += iv.w * wv.z; acc[3][3] += iv.w * wv.w;
        }

        float* part = gPart + kc * (BATCH * OUT_F) + rt * 64;
        #pragma unroll
        for (int bi = 0; bi < 4; bi++) {
            float4 v = make_float4(acc[bi][0], acc[bi][1], acc[bi][2], acc[bi][3]);
            *(float4*)(part + (b4 + bi) * OUT_F + r4) = v;
        }
    }
}

// ---------------------------------------------------------------------------
// K3: reduce 8 k-chunk partials + bias -> out (first 32768 floats), float4
// ---------------------------------------------------------------------------
__global__ void __launch_bounds__(256) k_reduce(const float* __restrict__ bias,
                                                float* __restrict__ outp) {
    const int t    = blockIdx.x * 256 + threadIdx.x;   // < 8192
    const int idx4 = t * 4;
    float4 s = *(const float4*)(bias + (idx4 & 511));
    #pragma unroll
    for (int kc = 0; kc < 8; kc++) {
        const float4 p = *(const float4*)(gPart + kc * (BATCH * OUT_F) + idx4);
        s.x += p.x; s.y += p.y; s.z += p.z; s.w += p.w;
    }
    *(float4*)(outp + idx4) = s;
}

// ---------------------------------------------------------------------------
// inputs: [0] inputs (64x512 f32), [1] grad (64x8x64x64 f32),
//         [2] W (512x512 f32), [3] diag_w (512 f32), [4] bias (512 f32)
// d_out:  out (64x512) followed by jac (64x8x64x64), f32
// ---------------------------------------------------------------------------
extern "C" void kernel_launch(void* const* d_in, const int* in_sizes, int n_in,
                              void* d_out, int out_size) {
    const float* inputs = (const float*)d_in[0];
    const float* grad   = (const float*)d_in[1];
    const float* W      = (const float*)d_in[2];
    const float* diag_w = (const float*)d_in[3];
    const float* bias   = (const float*)d_in[4];
    float* outp = (float*)d_out;

    k_weights<<<64 + 8, 256>>>(W, diag_w, inputs);
    k_main<<<512 + 64, 256>>>(grad, outp);
    k_reduce<<<32, 256>>>(bias, outp);
}